// round 16
// baseline (speedup 1.0000x reference)
#include <cuda_runtime.h>
#include <cstdint>

#define NT      9
#define SEQ     512
#define BATCH   64
#define EMB     1024
#define NQ      4
#define CHUNK_LEN 16
#define CPB     8
#define EMP     12

#define L2E 1.4426950408889634f
#define LN2 0.6931471805599453f

__device__ float g_M[BATCH * NQ * 81];
__device__ float g_num[BATCH];
__device__ int   g_cnt[BATCH];
__device__ int   g_ticket[BATCH];
__device__ int   g_tags64;

__device__ __forceinline__ void ffma2(unsigned long long& acc,
                                      unsigned long long a,
                                      unsigned long long b)
{
    asm("fma.rn.f32x2 %0, %1, %2, %3;" : "=l"(acc) : "l"(a), "l"(b), "l"(acc));
}
__device__ __forceinline__ unsigned long long dup2(float x)
{
    unsigned long long r; asm("mov.b64 %0, {%1,%1};" : "=l"(r) : "f"(x)); return r;
}
__device__ __forceinline__ float fast_ex2(float x)
{
    float r; asm("ex2.approx.ftz.f32 %0, %1;" : "=f"(r) : "f"(x)); return r;
}
__device__ __forceinline__ float fast_lg2(float x)
{
    float r; asm("lg2.approx.ftz.f32 %0, %1;" : "=f"(r) : "f"(x)); return r;
}
__device__ __forceinline__ void cp16(float* smem_dst, const float* gsrc)
{
    unsigned a = (unsigned)__cvta_generic_to_shared(smem_dst);
    asm volatile("cp.async.cg.shared.global [%0], [%1], 16;" :: "r"(a), "l"(gsrc));
}

// ---------------------------------------------------------------------------
// Kernel 1: emission = log_softmax(embed @ W^T + b)
// emis12 = emis11 with ONE syncthreads per tile: x TRIPLE-buffered via
// cp.async (issue for t+2 right after top-of-iter sync), W double-buffered
// and written for t+1 during compute of t. 16 syncs instead of 32.
// ---------------------------------------------------------------------------
__global__ __launch_bounds__(128) void emis12(
    const float* __restrict__ embed,
    const float* __restrict__ W,
    const float* __restrict__ bias,
    const unsigned* __restrict__ tags_words,
    float* __restrict__ out)
{
    __shared__ __align__(16) float sX[3 * 2176];   // 3 x (32 rows x 68)
    __shared__ __align__(16) float sWt[2 * 768];   // 2 x (64 x 12)

    const int tid = threadIdx.x;

    if (blockIdx.x == 0) {
        __shared__ int s_any;
        if (tid == 0) s_any = 0;
        __syncthreads();
        int nz = 0;
        for (int qq = tid; qq < 2048; qq += 128)
            nz |= (tags_words[2 * qq + 1] != 0u);
        if (nz) atomicOr(&s_any, 1);
        __syncthreads();
        if (tid == 0) {
            g_tags64 = s_any ? 0 : 1;
            out[0] = 0.0f;
        }
        if (tid < BATCH) {
            g_num[tid] = 0.0f;
            g_cnt[tid] = 0;
            g_ticket[tid] = 0;
        }
    }

    const int warp = tid >> 5;
    const int lane = tid & 31;
    const int p = lane & 15;               // rowpair: rows p, p+16
    const int s = warp * 2 + (lane >> 4);  // col slice 0..7 (8 cols/tile)
    const int rowBase = blockIdx.x * 32;
    const float* gbase = embed + (size_t)rowBase * EMB;

    // -------- prologue: async x tiles 0,1 ; W0 -> smem ; W1 -> regs --------
    {
#pragma unroll
        for (int it = 0; it < 4; ++it) {
            int idx = it * 128 + tid;
            int r2 = idx >> 4, cc = (idx & 15) * 4;
            cp16(&sX[r2 * 68 + cc], gbase + (size_t)r2 * EMB + cc);
        }
        asm volatile("cp.async.commit_group;");
#pragma unroll
        for (int it = 0; it < 4; ++it) {
            int idx = it * 128 + tid;
            int r2 = idx >> 4, cc = (idx & 15) * 4;
            cp16(&sX[2176 + r2 * 68 + cc], gbase + 64 + (size_t)r2 * EMB + cc);
        }
        asm volatile("cp.async.commit_group;");
    }
    float pw[5];
#pragma unroll
    for (int it = 0; it < 5; ++it) {           // W tile 0
        int idx = it * 128 + tid;
        if (idx < 576) {
            int t = idx >> 6, e = idx & 63;
            pw[it] = W[t * EMB + e];
        }
    }
#pragma unroll
    for (int it = 0; it < 5; ++it) {           // store W0 -> sWt[0]
        int idx = it * 128 + tid;
        if (idx < 576) {
            int t = idx >> 6, e = idx & 63;
            sWt[e * 12 + t] = pw[it];
        }
    }
#pragma unroll
    for (int it = 0; it < 5; ++it) {           // W tile 1 -> regs
        int idx = it * 128 + tid;
        if (idx < 576) {
            int t = idx >> 6, e = idx & 63;
            pw[it] = W[t * EMB + 64 + e];
        }
    }

    unsigned long long a01_0 = 0ull, a23_0 = 0ull, a45_0 = 0ull, a67_0 = 0ull;
    unsigned long long a01_1 = 0ull, a23_1 = 0ull, a45_1 = 0ull, a67_1 = 0ull;
    float a8_0 = 0.0f, a8_1 = 0.0f;

    for (int tile = 0; tile < 16; ++tile) {
        if (tile < 15) asm volatile("cp.async.wait_group 1;");
        else           asm volatile("cp.async.wait_group 0;");
        __syncthreads();   // x[tile] visible; W[tile] stored; old buffers free

        // issue x[tile+2] into its (just-freed) buffer
        if (tile + 2 < 16) {
            float* nbuf = &sX[((tile + 2) % 3) * 2176];
            const float* g = gbase + (tile + 2) * 64;
#pragma unroll
            for (int it = 0; it < 4; ++it) {
                int idx = it * 128 + tid;
                int r2 = idx >> 4, cc = (idx & 15) * 4;
                cp16(nbuf + r2 * 68 + cc, g + (size_t)r2 * EMB + cc);
            }
            asm volatile("cp.async.commit_group;");
        }
        // store W[tile+1] into the other W buffer (no reader until next sync)
        if (tile < 15) {
            float* wn = &sWt[((tile + 1) & 1) * 768];
#pragma unroll
            for (int it = 0; it < 5; ++it) {
                int idx = it * 128 + tid;
                if (idx < 576) {
                    int t = idx >> 6, e = idx & 63;
                    wn[e * 12 + t] = pw[it];
                }
            }
        }
        // prefetch W[tile+2] into regs
        if (tile + 2 < 16) {
#pragma unroll
            for (int it = 0; it < 5; ++it) {
                int idx = it * 128 + tid;
                if (idx < 576) {
                    int t = idx >> 6, e = idx & 63;
                    pw[it] = W[t * EMB + (tile + 2) * 64 + e];
                }
            }
        }

        // compute: 8 cols (slice s) x 2 rows (p, p+16)
        const float* xb  = &sX[(tile % 3) * 2176];
        const float* xr0 = xb + p * 68 + s * 8;
        const float* xr1 = xb + (p + 16) * 68 + s * 8;
        const float* wq  = &sWt[(tile & 1) * 768] + (s * 8) * 12;
#pragma unroll
        for (int e4 = 0; e4 < 8; e4 += 4) {
            float4 xa4 = *(const float4*)(xr0 + e4);
            float4 xb4 = *(const float4*)(xr1 + e4);
#pragma unroll
            for (int u = 0; u < 4; ++u) {
                float xa = (u == 0) ? xa4.x : (u == 1) ? xa4.y : (u == 2) ? xa4.z : xa4.w;
                float xv = (u == 0) ? xb4.x : (u == 1) ? xb4.y : (u == 2) ? xb4.z : xb4.w;
                const float* we = wq + (e4 + u) * 12;
                ulonglong2 wA = *(const ulonglong2*)we;
                ulonglong2 wB = *(const ulonglong2*)(we + 4);
                float w8 = we[8];
                unsigned long long da = dup2(xa);
                unsigned long long db = dup2(xv);
                ffma2(a01_0, da, wA.x); ffma2(a23_0, da, wA.y);
                ffma2(a45_0, da, wB.x); ffma2(a67_0, da, wB.y);
                a8_0 = fmaf(xa, w8, a8_0);
                ffma2(a01_1, db, wA.x); ffma2(a23_1, db, wA.y);
                ffma2(a45_1, db, wB.x); ffma2(a67_1, db, wB.y);
                a8_1 = fmaf(xv, w8, a8_1);
            }
        }
        // no trailing sync: next iteration's top sync provides it
    }

    // -------- reduction across slices + log_softmax --------
    __syncthreads();                 // everyone done computing; reuse sX
    float* red = sX;                 // red[row][73]
    {
        float2 f;
        float* r0 = &red[p * 73 + s * 9];
        f = *(float2*)&a01_0; r0[0] = f.x; r0[1] = f.y;
        f = *(float2*)&a23_0; r0[2] = f.x; r0[3] = f.y;
        f = *(float2*)&a45_0; r0[4] = f.x; r0[5] = f.y;
        f = *(float2*)&a67_0; r0[6] = f.x; r0[7] = f.y;
        r0[8] = a8_0;
        float* r1 = &red[(p + 16) * 73 + s * 9];
        f = *(float2*)&a01_1; r1[0] = f.x; r1[1] = f.y;
        f = *(float2*)&a23_1; r1[2] = f.x; r1[3] = f.y;
        f = *(float2*)&a45_1; r1[4] = f.x; r1[5] = f.y;
        f = *(float2*)&a67_1; r1[6] = f.x; r1[7] = f.y;
        r1[8] = a8_1;
    }
    __syncthreads();

    if (tid < 32) {
        const float* rp = &red[tid * 73];
        float acc[NT];
#pragma unroll
        for (int t = 0; t < NT; t++) {
            float sum = bias[t];
#pragma unroll
            for (int qq = 0; qq < 8; qq++) sum += rp[qq * 9 + t];
            acc[t] = sum;
        }

        float mx = acc[0];
#pragma unroll
        for (int t = 1; t < NT; t++) mx = fmaxf(mx, acc[t]);
        float sum = 0.0f;
#pragma unroll
        for (int t = 0; t < NT; t++) sum += fast_ex2((acc[t] - mx) * L2E);
        float lse = fmaf(fast_lg2(sum), LN2, mx);

        float* o = out + 1 + (size_t)(rowBase + tid) * NT;
#pragma unroll
        for (int t = 0; t < NT; t++) o[t] = acc[t] - lse;
    }
}

// ---------------------------------------------------------------------------
// Kernel 2: CRF scan + fused finalize, linear-domain scan with ffma2-packed
// matvec (4 ffma2 + 1 fma per k instead of 9 FFMA). R14 config: 96 threads,
// 8 chunks x 16 steps; float4 emission staging; 3-level tree combine.
// ---------------------------------------------------------------------------
__global__ __launch_bounds__(96) void crf_scan_fin(
    float* __restrict__ outbuf,
    const void* __restrict__ tags,
    const int*  __restrict__ mask,
    const float* __restrict__ startT,
    const float* __restrict__ endT,
    const float* __restrict__ trans)
{
    const float* emis = outbuf + 1;
    const int q = blockIdx.x, b = blockIdx.y;
    const int tid = threadIdx.x;
    const int lane = tid & 31;

    __shared__ __align__(16) float sEm[128 * EMP];
    __shared__ __align__(16) float sEx[128 * EMP];
    __shared__ int   sMk[128];
    __shared__ float sTr[84];
    __shared__ __align__(16) float sE2[112];
    __shared__ __align__(16) float sMt[CPB][84];
    __shared__ __align__(16) float sEB[4][112];
    __shared__ float s_accf;
    __shared__ int   s_msum;
    __shared__ int   s_last;

    const int t0_blk = 1 + q * 128;
    const int n = min(SEQ - t0_blk, 128);

    const float* em_b = emis + (size_t)b * SEQ * NT;
    const float* em_q = em_b + (size_t)t0_blk * NT;
    const int*   mk   = mask + b * SEQ + t0_blk;

    if (tid == 0) { s_accf = 0.0f; s_msum = 0; }
    // float4 emission staging + ex2 transform
    {
        const int tot = n * NT;
        const int g4  = (tot + 3) >> 2;
        for (int g = tid; g < g4; g += 96) {
            float4 v = *(const float4*)(em_q + g * 4);
#pragma unroll
            for (int u = 0; u < 4; ++u) {
                int idx = g * 4 + u;
                if (idx < tot) {
                    float ev = (u == 0) ? v.x : (u == 1) ? v.y : (u == 2) ? v.z : v.w;
                    int t = idx / NT, j = idx - t * NT;
                    sEm[t * EMP + j] = ev;
                    sEx[t * EMP + j] = fast_ex2(ev * L2E);
                }
            }
        }
    }
    for (int idx = tid; idx < n; idx += 96) sMk[idx] = mk[idx];
    if (tid < 81) {
        float tv = trans[tid];
        sTr[tid] = tv;
        int k = tid / 9, j = tid - k * 9;
        sE2[k * 12 + j] = fast_ex2(tv * L2E);
    }
    __syncthreads();

    // ---- chunk scans: 72 threads = 8 chunks x 9 rows, linear, ffma2 ----
    if (tid < CPB * NT) {
        const int c = tid / NT;
        const int i = tid - c * NT;

        float u[9];
        float corr = 0.0f;
        bool started = false;

        const int s0 = c * CHUNK_LEN;
        const int s1 = min(n, s0 + CHUNK_LEN);

        for (int s = s0; s < s1; ++s) {
            const int m = sMk[s];
            float4 x0 = *(const float4*)&sEx[s * EMP];
            float4 x4 = *(const float4*)&sEx[s * EMP + 4];
            float  x8 = sEx[s * EMP + 8];
            float ex[9] = {x0.x, x0.y, x0.z, x0.w, x4.x, x4.y, x4.z, x4.w, x8};
            if (m) {
                if (!started) {
#pragma unroll
                    for (int j = 0; j < 9; j++) u[j] = sE2[i * 12 + j] * ex[j];
                    started = true;
                } else {
                    unsigned long long acc01 = 0ull, acc23 = 0ull,
                                       acc45 = 0ull, acc67 = 0ull;
                    float acc8 = 0.0f;
#pragma unroll
                    for (int k = 0; k < 9; k++) {
                        const float* we = &sE2[k * 12];
                        ulonglong2 wA = *(const ulonglong2*)we;
                        ulonglong2 wB = *(const ulonglong2*)(we + 4);
                        float w8 = we[8];
                        unsigned long long duk = dup2(u[k]);
                        ffma2(acc01, duk, wA.x); ffma2(acc23, duk, wA.y);
                        ffma2(acc45, duk, wB.x); ffma2(acc67, duk, wB.y);
                        acc8 = fmaf(u[k], w8, acc8);
                    }
                    float2 f;
                    f = *(float2*)&acc01; u[0] = f.x * ex[0]; u[1] = f.y * ex[1];
                    f = *(float2*)&acc23; u[2] = f.x * ex[2]; u[3] = f.y * ex[3];
                    f = *(float2*)&acc45; u[4] = f.x * ex[4]; u[5] = f.y * ex[5];
                    f = *(float2*)&acc67; u[6] = f.x * ex[6]; u[7] = f.y * ex[7];
                    u[8] = acc8 * ex[8];
                }
            }
            if (s == s0 + 7 && started) {          // underflow guard
                float mxu = u[0];
#pragma unroll
                for (int j = 1; j < 9; j++) mxu = fmaxf(mxu, u[j]);
                if (mxu < 1e-10f) {
#pragma unroll
                    for (int j = 0; j < 9; j++) u[j] *= 1e10f;
                    corr -= 23.025850930f;
                }
            }
        }
#pragma unroll
        for (int j = 0; j < 9; j++)
            sMt[c][i * 9 + j] = started
                ? (fmaf(fast_lg2(u[j]), LN2, corr))
                : ((i == j) ? 0.0f : -1e30f);
    }

    // ---- numerator contribution for this quarter ----
    {
        const long long* t64 = (const long long*)tags;
        const int*       t32 = (const int*)tags;
        const int is64 = g_tags64;

        float acc = 0.0f;
        int   msum = 0;
        for (int idx = tid; idx < n; idx += 96) {
            const int s = t0_blk + idx;
            const int m = sMk[idx];
            msum += m;
            int tp  = is64 ? (int)t64[b * SEQ + s - 1] : t32[b * SEQ + s - 1];
            int tcu = is64 ? (int)t64[b * SEQ + s]     : t32[b * SEQ + s];
            acc += (float)m * (sTr[tp * 9 + tcu] + sEm[idx * EMP + tcu]);
        }
        if (q == 0 && tid == 0) msum += mask[b * SEQ];
#pragma unroll
        for (int o = 16; o > 0; o >>= 1) {
            acc  += __shfl_down_sync(0xffffffffu, acc, o);
            msum += __shfl_down_sync(0xffffffffu, msum, o);
        }
        if (lane == 0) {
            atomicAdd(&s_accf, acc);
            atomicAdd(&s_msum, msum);
        }
    }

    // ---- tree combine: 8 -> 4 -> 2 -> 1 (log domain, ffma2) ----
#pragma unroll
    for (int lvl = 0; lvl < 3; ++lvl) {
        const int np = 4 >> lvl;
        const int active = np * NT;
        __syncthreads();
        if (tid < active) {
            const int pp = tid / NT, i = tid - (tid / NT) * NT;
            const float* Br = &sMt[2 * pp + 1][i * 9];
#pragma unroll
            for (int j = 0; j < 9; j++)
                sEB[pp][i * 12 + j] = fast_ex2(Br[j] * L2E);
        }
        __syncthreads();
        float C[9];
        int pp = 0, i = 0;
        if (tid < active) {
            pp = tid / NT; i = tid - pp * NT;
            const float* Ar = &sMt[2 * pp][i * 9];
            float a[9];
#pragma unroll
            for (int k = 0; k < 9; k++) a[k] = Ar[k];
            float r = a[0];
#pragma unroll
            for (int k = 1; k < 9; k++) r = fmaxf(r, a[k]);
            float e[9];
#pragma unroll
            for (int k = 0; k < 9; k++) e[k] = fast_ex2((a[k] - r) * L2E);
            unsigned long long acc01 = 0ull, acc23 = 0ull,
                               acc45 = 0ull, acc67 = 0ull;
            float acc8 = 0.0f;
#pragma unroll
            for (int k = 0; k < 9; k++) {
                const float* we = &sEB[pp][k * 12];
                ulonglong2 wA = *(const ulonglong2*)we;
                ulonglong2 wB = *(const ulonglong2*)(we + 4);
                float w8 = we[8];
                unsigned long long dek = dup2(e[k]);
                ffma2(acc01, dek, wA.x); ffma2(acc23, dek, wA.y);
                ffma2(acc45, dek, wB.x); ffma2(acc67, dek, wB.y);
                acc8 = fmaf(e[k], w8, acc8);
            }
            float2 f;
            f = *(float2*)&acc01; C[0] = fmaf(fast_lg2(f.x), LN2, r); C[1] = fmaf(fast_lg2(f.y), LN2, r);
            f = *(float2*)&acc23; C[2] = fmaf(fast_lg2(f.x), LN2, r); C[3] = fmaf(fast_lg2(f.y), LN2, r);
            f = *(float2*)&acc45; C[4] = fmaf(fast_lg2(f.x), LN2, r); C[5] = fmaf(fast_lg2(f.y), LN2, r);
            f = *(float2*)&acc67; C[6] = fmaf(fast_lg2(f.x), LN2, r); C[7] = fmaf(fast_lg2(f.y), LN2, r);
            C[8] = fmaf(fast_lg2(acc8), LN2, r);
        }
        __syncthreads();
        if (tid < active) {
#pragma unroll
            for (int j = 0; j < 9; j++) sMt[pp][i * 9 + j] = C[j];
        }
    }
    __syncthreads();

    if (tid < 81) g_M[(b * NQ + q) * 81 + tid] = sMt[0][tid];
    if (tid == 0) {
        atomicAdd(&g_num[b], s_accf);
        atomicAdd(&g_cnt[b], s_msum);
        __threadfence();
        int old = atomicAdd(&g_ticket[b], 1);
        s_last = (old == NQ - 1);
    }
    __syncthreads();

    if (s_last && tid < 32) {
        __threadfence();
        const long long* t64 = (const long long*)tags;
        const int*       t32 = (const int*)tags;
        const int is64 = g_tags64;

        const int j = tid;
        float v = (j < 9) ? (startT[j] + em_b[j]) : -1e30f;
        for (int c = 0; c < NQ; c++) {
            const float* Mc = g_M + (b * NQ + c) * 81;
            float vals[9];
#pragma unroll
            for (int i2 = 0; i2 < 9; i2++) {
                float sv = __shfl_sync(0xffffffffu, v, i2);
                vals[i2] = sv + ((j < 9) ? Mc[i2 * 9 + j] : 0.0f);
            }
            float nv = -1e30f;
            if (j < 9) {
                float mx = vals[0];
#pragma unroll
                for (int i2 = 1; i2 < 9; i2++) mx = fmaxf(mx, vals[i2]);
                float s = 0.0f;
#pragma unroll
                for (int i2 = 0; i2 < 9; i2++) s += fast_ex2((vals[i2] - mx) * L2E);
                nv = fmaf(fast_lg2(s), LN2, mx);
            }
            v = nv;
        }
        float x = (j < 9) ? v + endT[j] : -1e30f;
        float mx = x;
#pragma unroll
        for (int o = 16; o > 0; o >>= 1) mx = fmaxf(mx, __shfl_xor_sync(0xffffffffu, mx, o));
        float e = (j < 9) ? fast_ex2((x - mx) * L2E) : 0.0f;
#pragma unroll
        for (int o = 16; o > 0; o >>= 1) e += __shfl_xor_sync(0xffffffffu, e, o);
        if (tid == 0) {
            float den = fmaf(fast_lg2(e), LN2, mx);
            int tg0  = is64 ? (int)t64[b * SEQ] : t32[b * SEQ];
            int last = g_cnt[b] - 1;
            int tl   = is64 ? (int)t64[b * SEQ + last] : t32[b * SEQ + last];
            float num = g_num[b] + startT[tg0] + em_b[tg0] + endT[tl];
            atomicAdd(outbuf, num - den);
        }
    }
}

// ---------------------------------------------------------------------------
extern "C" void kernel_launch(void* const* d_in, const int* in_sizes, int n_in,
                              void* d_out, int out_size)
{
    const float* embed  = (const float*)d_in[0];
    const void*  tags   = d_in[1];
    const int*   mask   = (const int*)d_in[2];
    const float* W      = (const float*)d_in[3];
    const float* bias   = (const float*)d_in[4];
    const float* startT = (const float*)d_in[5];
    const float* endT   = (const float*)d_in[6];
    const float* trans  = (const float*)d_in[7];
    float* out = (float*)d_out;

    emis12<<<(BATCH * SEQ) / 32, 128>>>(embed, W, bias,
                                        (const unsigned*)tags, out);
    dim3 g2(NQ, BATCH);
    crf_scan_fin<<<g2, 96>>>(out, tags, mask, startT, endT, trans);
}

// round 17
// speedup vs baseline: 1.0254x; 1.0254x over previous
#include <cuda_runtime.h>
#include <cstdint>

#define NT      9
#define SEQ     512
#define BATCH   64
#define EMB     1024
#define NQ      8               // sequence eighths (scan blocks per batch)
#define CHUNK_LEN 8
#define CPB     8
#define EMP     12

#define L2E 1.4426950408889634f
#define LN2 0.6931471805599453f

__device__ float g_M[BATCH * NQ * 81];
__device__ float g_num[BATCH];
__device__ int   g_cnt[BATCH];
__device__ int   g_ticket[BATCH];
__device__ int   g_tags64;

__device__ __forceinline__ void ffma2(unsigned long long& acc,
                                      unsigned long long a,
                                      unsigned long long b)
{
    asm("fma.rn.f32x2 %0, %1, %2, %3;" : "=l"(acc) : "l"(a), "l"(b), "l"(acc));
}
__device__ __forceinline__ unsigned long long dup2(float x)
{
    unsigned long long r; asm("mov.b64 %0, {%1,%1};" : "=l"(r) : "f"(x)); return r;
}
__device__ __forceinline__ float fast_ex2(float x)
{
    float r; asm("ex2.approx.ftz.f32 %0, %1;" : "=f"(r) : "f"(x)); return r;
}
__device__ __forceinline__ float fast_lg2(float x)
{
    float r; asm("lg2.approx.ftz.f32 %0, %1;" : "=f"(r) : "f"(x)); return r;
}
__device__ __forceinline__ void cp16(float* smem_dst, const float* gsrc)
{
    unsigned a = (unsigned)__cvta_generic_to_shared(smem_dst);
    asm volatile("cp.async.cg.shared.global [%0], [%1], 16;" :: "r"(a), "l"(gsrc));
}

// ---------------------------------------------------------------------------
// Kernel 1 (PROVEN emis11, R14): emission = log_softmax(embed @ W^T + b)
// ---------------------------------------------------------------------------
__global__ __launch_bounds__(128) void emis11(
    const float* __restrict__ embed,
    const float* __restrict__ W,
    const float* __restrict__ bias,
    const unsigned* __restrict__ tags_words,
    float* __restrict__ out)
{
    __shared__ __align__(16) float sX[2 * 2176];   // 2 x (32 rows x 68)
    __shared__ __align__(16) float sWt[2 * 768];   // 2 x (64 x 12)

    const int tid = threadIdx.x;

    if (blockIdx.x == 0) {
        __shared__ int s_any;
        if (tid == 0) s_any = 0;
        __syncthreads();
        int nz = 0;
        for (int qq = tid; qq < 2048; qq += 128)
            nz |= (tags_words[2 * qq + 1] != 0u);
        if (nz) atomicOr(&s_any, 1);
        __syncthreads();
        if (tid == 0) {
            g_tags64 = s_any ? 0 : 1;
            out[0] = 0.0f;
        }
        if (tid < BATCH) {
            g_num[tid] = 0.0f;
            g_cnt[tid] = 0;
            g_ticket[tid] = 0;
        }
    }

    const int warp = tid >> 5;
    const int lane = tid & 31;
    const int p = lane & 15;
    const int s = warp * 2 + (lane >> 4);
    const int rowBase = blockIdx.x * 32;
    const float* gbase = embed + (size_t)rowBase * EMB;

    {
#pragma unroll
        for (int it = 0; it < 4; ++it) {
            int idx = it * 128 + tid;
            int r2 = idx >> 4, cc = (idx & 15) * 4;
            cp16(&sX[r2 * 68 + cc], gbase + (size_t)r2 * EMB + cc);
        }
        asm volatile("cp.async.commit_group;");
#pragma unroll
        for (int it = 0; it < 4; ++it) {
            int idx = it * 128 + tid;
            int r2 = idx >> 4, cc = (idx & 15) * 4;
            cp16(&sX[2176 + r2 * 68 + cc], gbase + 64 + (size_t)r2 * EMB + cc);
        }
        asm volatile("cp.async.commit_group;");
    }
    float pw[5];
#pragma unroll
    for (int it = 0; it < 5; ++it) {
        int idx = it * 128 + tid;
        if (idx < 576) {
            int t = idx >> 6, e = idx & 63;
            pw[it] = W[t * EMB + e];
        }
    }

    unsigned long long a01_0 = 0ull, a23_0 = 0ull, a45_0 = 0ull, a67_0 = 0ull;
    unsigned long long a01_1 = 0ull, a23_1 = 0ull, a45_1 = 0ull, a67_1 = 0ull;
    float a8_0 = 0.0f, a8_1 = 0.0f;

    for (int tile = 0; tile < 16; ++tile) {
        if (tile < 15) asm volatile("cp.async.wait_group 1;");
        else           asm volatile("cp.async.wait_group 0;");
        __syncthreads();

        float* wbuf = &sWt[(tile & 1) * 768];
#pragma unroll
        for (int it = 0; it < 5; ++it) {
            int idx = it * 128 + tid;
            if (idx < 576) {
                int t = idx >> 6, e = idx & 63;
                wbuf[e * 12 + t] = pw[it];
            }
        }
        if (tile < 15) {
#pragma unroll
            for (int it = 0; it < 5; ++it) {
                int idx = it * 128 + tid;
                if (idx < 576) {
                    int t = idx >> 6, e = idx & 63;
                    pw[it] = W[t * EMB + (tile + 1) * 64 + e];
                }
            }
        }
        __syncthreads();

        const float* xb  = &sX[(tile & 1) * 2176];
        const float* xr0 = xb + p * 68 + s * 8;
        const float* xr1 = xb + (p + 16) * 68 + s * 8;
        const float* wq  = wbuf + (s * 8) * 12;
#pragma unroll
        for (int e4 = 0; e4 < 8; e4 += 4) {
            float4 xa4 = *(const float4*)(xr0 + e4);
            float4 xb4 = *(const float4*)(xr1 + e4);
#pragma unroll
            for (int u = 0; u < 4; ++u) {
                float xa = (u == 0) ? xa4.x : (u == 1) ? xa4.y : (u == 2) ? xa4.z : xa4.w;
                float xv = (u == 0) ? xb4.x : (u == 1) ? xb4.y : (u == 2) ? xb4.z : xb4.w;
                const float* we = wq + (e4 + u) * 12;
                ulonglong2 wA = *(const ulonglong2*)we;
                ulonglong2 wB = *(const ulonglong2*)(we + 4);
                float w8 = we[8];
                unsigned long long da = dup2(xa);
                unsigned long long db = dup2(xv);
                ffma2(a01_0, da, wA.x); ffma2(a23_0, da, wA.y);
                ffma2(a45_0, da, wB.x); ffma2(a67_0, da, wB.y);
                a8_0 = fmaf(xa, w8, a8_0);
                ffma2(a01_1, db, wA.x); ffma2(a23_1, db, wA.y);
                ffma2(a45_1, db, wB.x); ffma2(a67_1, db, wB.y);
                a8_1 = fmaf(xv, w8, a8_1);
            }
        }
        __syncthreads();

        if (tile + 2 < 16) {
            float* nbuf = &sX[(tile & 1) * 2176];
            const float* g = gbase + (tile + 2) * 64;
#pragma unroll
            for (int it = 0; it < 4; ++it) {
                int idx = it * 128 + tid;
                int r2 = idx >> 4, cc = (idx & 15) * 4;
                cp16(nbuf + r2 * 68 + cc, g + (size_t)r2 * EMB + cc);
            }
            asm volatile("cp.async.commit_group;");
        }
    }

    float* red = sX;
    {
        float2 f;
        float* r0 = &red[p * 73 + s * 9];
        f = *(float2*)&a01_0; r0[0] = f.x; r0[1] = f.y;
        f = *(float2*)&a23_0; r0[2] = f.x; r0[3] = f.y;
        f = *(float2*)&a45_0; r0[4] = f.x; r0[5] = f.y;
        f = *(float2*)&a67_0; r0[6] = f.x; r0[7] = f.y;
        r0[8] = a8_0;
        float* r1 = &red[(p + 16) * 73 + s * 9];
        f = *(float2*)&a01_1; r1[0] = f.x; r1[1] = f.y;
        f = *(float2*)&a23_1; r1[2] = f.x; r1[3] = f.y;
        f = *(float2*)&a45_1; r1[4] = f.x; r1[5] = f.y;
        f = *(float2*)&a67_1; r1[6] = f.x; r1[7] = f.y;
        r1[8] = a8_1;
    }
    __syncthreads();

    if (tid < 32) {
        const float* rp = &red[tid * 73];
        float acc[NT];
#pragma unroll
        for (int t = 0; t < NT; t++) {
            float sum = bias[t];
#pragma unroll
            for (int qq = 0; qq < 8; qq++) sum += rp[qq * 9 + t];
            acc[t] = sum;
        }

        float mx = acc[0];
#pragma unroll
        for (int t = 1; t < NT; t++) mx = fmaxf(mx, acc[t]);
        float sum = 0.0f;
#pragma unroll
        for (int t = 0; t < NT; t++) sum += fast_ex2((acc[t] - mx) * L2E);
        float lse = fmaf(fast_lg2(sum), LN2, mx);

        float* o = out + 1 + (size_t)(rowBase + tid) * NT;
#pragma unroll
        for (int t = 0; t < NT; t++) o[t] = acc[t] - lse;
    }
}

// ---------------------------------------------------------------------------
// Kernel 2: CRF scan + fused finalize, linear-domain scan (R14 body).
// R17: NQ=8 (512 blocks, halved per-block work: 64 positions, 8 chunks x
// 8 steps). Numerator reads its single log-emission from global (L2-hot);
// only exp(emissions) staged in smem.
// ---------------------------------------------------------------------------
__global__ __launch_bounds__(96) void crf_scan_fin(
    float* __restrict__ outbuf,
    const void* __restrict__ tags,
    const int*  __restrict__ mask,
    const float* __restrict__ startT,
    const float* __restrict__ endT,
    const float* __restrict__ trans)
{
    const float* emis = outbuf + 1;
    const int q = blockIdx.x, b = blockIdx.y;
    const int tid = threadIdx.x;
    const int lane = tid & 31;

    __shared__ __align__(16) float sEx[64 * EMP];    // exp(emissions)
    __shared__ int   sMk[64];
    __shared__ float sTr[84];
    __shared__ __align__(16) float sE2[112];         // exp(trans) [k][12]
    __shared__ __align__(16) float sMt[CPB][84];
    __shared__ __align__(16) float sEB[4][112];
    __shared__ float s_accf;
    __shared__ int   s_msum;
    __shared__ int   s_last;

    const int t0_blk = (q == 0) ? 1 : q * 64;
    const int n = (q == 0) ? 63 : 64;                // covers 1..511

    const float* em_b = emis + (size_t)b * SEQ * NT;
    const float* em_q = em_b + (size_t)t0_blk * NT;
    const int*   mk   = mask + b * SEQ + t0_blk;

    if (tid == 0) { s_accf = 0.0f; s_msum = 0; }
    for (int idx = tid; idx < n * NT; idx += 96) {
        int t = idx / NT, j = idx - t * NT;
        sEx[t * EMP + j] = fast_ex2(em_q[idx] * L2E);
    }
    for (int idx = tid; idx < n; idx += 96) sMk[idx] = mk[idx];
    if (tid < 81) {
        float tv = trans[tid];
        sTr[tid] = tv;
        int k = tid / 9, j = tid - k * 9;
        sE2[k * 12 + j] = fast_ex2(tv * L2E);
    }
    __syncthreads();

    // ---- chunk scans: 72 threads = 8 chunks x 8 steps, linear domain ----
    if (tid < CPB * NT) {
        const int c = tid / NT;
        const int i = tid - c * NT;

        float u[9];
        float corr = 0.0f;
        bool started = false;

        const int s0 = c * CHUNK_LEN;
        const int s1 = min(n, s0 + CHUNK_LEN);

        for (int s = s0; s < s1; ++s) {
            const int m = sMk[s];
            float4 x0 = *(const float4*)&sEx[s * EMP];
            float4 x4 = *(const float4*)&sEx[s * EMP + 4];
            float  x8 = sEx[s * EMP + 8];
            float ex[9] = {x0.x, x0.y, x0.z, x0.w, x4.x, x4.y, x4.z, x4.w, x8};
            if (m) {
                if (!started) {
#pragma unroll
                    for (int j = 0; j < 9; j++) u[j] = sE2[i * 12 + j] * ex[j];
                    started = true;
                } else {
                    float acc[9];
#pragma unroll
                    for (int j = 0; j < 9; j++) acc[j] = 0.0f;
#pragma unroll
                    for (int k = 0; k < 9; k++) {
                        float4 b0 = *(const float4*)&sE2[k * 12];
                        float4 b4 = *(const float4*)&sE2[k * 12 + 4];
                        float  b8 = sE2[k * 12 + 8];
                        acc[0] = fmaf(u[k], b0.x, acc[0]);
                        acc[1] = fmaf(u[k], b0.y, acc[1]);
                        acc[2] = fmaf(u[k], b0.z, acc[2]);
                        acc[3] = fmaf(u[k], b0.w, acc[3]);
                        acc[4] = fmaf(u[k], b4.x, acc[4]);
                        acc[5] = fmaf(u[k], b4.y, acc[5]);
                        acc[6] = fmaf(u[k], b4.z, acc[6]);
                        acc[7] = fmaf(u[k], b4.w, acc[7]);
                        acc[8] = fmaf(u[k], b8,   acc[8]);
                    }
#pragma unroll
                    for (int j = 0; j < 9; j++) u[j] = acc[j] * ex[j];
                }
            }
            if (s == s0 + 4 && started) {            // underflow guard
                float mxu = u[0];
#pragma unroll
                for (int j = 1; j < 9; j++) mxu = fmaxf(mxu, u[j]);
                if (mxu < 1e-10f) {
#pragma unroll
                    for (int j = 0; j < 9; j++) u[j] *= 1e10f;
                    corr -= 23.025850930f;
                }
            }
        }
#pragma unroll
        for (int j = 0; j < 9; j++)
            sMt[c][i * 9 + j] = started
                ? (fmaf(fast_lg2(u[j]), LN2, corr))
                : ((i == j) ? 0.0f : -1e30f);
    }

    // ---- numerator contribution (log emission read directly from global) ----
    {
        const long long* t64 = (const long long*)tags;
        const int*       t32 = (const int*)tags;
        const int is64 = g_tags64;

        float acc = 0.0f;
        int   msum = 0;
        for (int idx = tid; idx < n; idx += 96) {
            const int s = t0_blk + idx;              // global position >= 1
            const int m = sMk[idx];
            msum += m;
            int tp  = is64 ? (int)t64[b * SEQ + s - 1] : t32[b * SEQ + s - 1];
            int tcu = is64 ? (int)t64[b * SEQ + s]     : t32[b * SEQ + s];
            acc += (float)m * (sTr[tp * 9 + tcu] + em_q[idx * NT + tcu]);
        }
        if (q == 0 && tid == 0) msum += mask[b * SEQ];
#pragma unroll
        for (int o = 16; o > 0; o >>= 1) {
            acc  += __shfl_down_sync(0xffffffffu, acc, o);
            msum += __shfl_down_sync(0xffffffffu, msum, o);
        }
        if (lane == 0) {
            atomicAdd(&s_accf, acc);
            atomicAdd(&s_msum, msum);
        }
    }

    // ---- tree combine: 8 -> 4 -> 2 -> 1 (log domain) ----
#pragma unroll
    for (int lvl = 0; lvl < 3; ++lvl) {
        const int np = 4 >> lvl;
        const int active = np * NT;
        __syncthreads();
        if (tid < active) {
            const int pp = tid / NT, i = tid - (tid / NT) * NT;
            const float* Br = &sMt[2 * pp + 1][i * 9];
#pragma unroll
            for (int j = 0; j < 9; j++)
                sEB[pp][i * 12 + j] = fast_ex2(Br[j] * L2E);
        }
        __syncthreads();
        float C[9];
        int pp = 0, i = 0;
        if (tid < active) {
            pp = tid / NT; i = tid - pp * NT;
            const float* Ar = &sMt[2 * pp][i * 9];
            float a[9];
#pragma unroll
            for (int k = 0; k < 9; k++) a[k] = Ar[k];
            float r = a[0];
#pragma unroll
            for (int k = 1; k < 9; k++) r = fmaxf(r, a[k]);
            float e[9];
#pragma unroll
            for (int k = 0; k < 9; k++) e[k] = fast_ex2((a[k] - r) * L2E);
            float acc[9];
#pragma unroll
            for (int j = 0; j < 9; j++) acc[j] = 0.0f;
#pragma unroll
            for (int k = 0; k < 9; k++) {
                float4 b0 = *(const float4*)&sEB[pp][k * 12];
                float4 b4 = *(const float4*)&sEB[pp][k * 12 + 4];
                float  b8 = sEB[pp][k * 12 + 8];
                acc[0] = fmaf(e[k], b0.x, acc[0]);
                acc[1] = fmaf(e[k], b0.y, acc[1]);
                acc[2] = fmaf(e[k], b0.z, acc[2]);
                acc[3] = fmaf(e[k], b0.w, acc[3]);
                acc[4] = fmaf(e[k], b4.x, acc[4]);
                acc[5] = fmaf(e[k], b4.y, acc[5]);
                acc[6] = fmaf(e[k], b4.z, acc[6]);
                acc[7] = fmaf(e[k], b4.w, acc[7]);
                acc[8] = fmaf(e[k], b8,   acc[8]);
            }
#pragma unroll
            for (int j = 0; j < 9; j++) C[j] = fmaf(fast_lg2(acc[j]), LN2, r);
        }
        __syncthreads();
        if (tid < active) {
#pragma unroll
            for (int j = 0; j < 9; j++) sMt[pp][i * 9 + j] = C[j];
        }
    }
    __syncthreads();

    if (tid < 81) g_M[(b * NQ + q) * 81 + tid] = sMt[0][tid];
    if (tid == 0) {
        atomicAdd(&g_num[b], s_accf);
        atomicAdd(&g_cnt[b], s_msum);
        __threadfence();
        int old = atomicAdd(&g_ticket[b], 1);
        s_last = (old == NQ - 1);
    }
    __syncthreads();

    if (s_last && tid < 32) {
        __threadfence();
        const long long* t64 = (const long long*)tags;
        const int*       t32 = (const int*)tags;
        const int is64 = g_tags64;

        const int j = tid;
        float v = (j < 9) ? (startT[j] + em_b[j]) : -1e30f;
        for (int c = 0; c < NQ; c++) {
            const float* Mc = g_M + (b * NQ + c) * 81;
            float vals[9];
#pragma unroll
            for (int i2 = 0; i2 < 9; i2++) {
                float sv = __shfl_sync(0xffffffffu, v, i2);
                vals[i2] = sv + ((j < 9) ? Mc[i2 * 9 + j] : 0.0f);
            }
            float nv = -1e30f;
            if (j < 9) {
                float mx = vals[0];
#pragma unroll
                for (int i2 = 1; i2 < 9; i2++) mx = fmaxf(mx, vals[i2]);
                float s = 0.0f;
#pragma unroll
                for (int i2 = 0; i2 < 9; i2++) s += fast_ex2((vals[i2] - mx) * L2E);
                nv = fmaf(fast_lg2(s), LN2, mx);
            }
            v = nv;
        }
        float x = (j < 9) ? v + endT[j] : -1e30f;
        float mx = x;
#pragma unroll
        for (int o = 16; o > 0; o >>= 1) mx = fmaxf(mx, __shfl_xor_sync(0xffffffffu, mx, o));
        float e = (j < 9) ? fast_ex2((x - mx) * L2E) : 0.0f;
#pragma unroll
        for (int o = 16; o > 0; o >>= 1) e += __shfl_xor_sync(0xffffffffu, e, o);
        if (tid == 0) {
            float den = fmaf(fast_lg2(e), LN2, mx);
            int tg0  = is64 ? (int)t64[b * SEQ] : t32[b * SEQ];
            int last = g_cnt[b] - 1;
            int tl   = is64 ? (int)t64[b * SEQ + last] : t32[b * SEQ + last];
            float num = g_num[b] + startT[tg0] + em_b[tg0] + endT[tl];
            atomicAdd(outbuf, num - den);
        }
    }
}

// ---------------------------------------------------------------------------
extern "C" void kernel_launch(void* const* d_in, const int* in_sizes, int n_in,
                              void* d_out, int out_size)
{
    const float* embed  = (const float*)d_in[0];
    const void*  tags   = d_in[1];
    const int*   mask   = (const int*)d_in[2];
    const float* W      = (const float*)d_in[3];
    const float* bias   = (const float*)d_in[4];
    const float* startT = (const float*)d_in[5];
    const float* endT   = (const float*)d_in[6];
    const float* trans  = (const float*)d_in[7];
    float* out = (float*)d_out;

    emis11<<<(BATCH * SEQ) / 32, 128>>>(embed, W, bias,
                                        (const unsigned*)tags, out);
    dim3 g2(NQ, BATCH);
    crf_scan_fin<<<g2, 96>>>(out, tags, mask, startT, endT, trans);
}